// round 7
// baseline (speedup 1.0000x reference)
#include <cuda_runtime.h>
#include <cuda_fp16.h>
#include <math.h>

#define NN 50000
#define NE 800000
#define DIM 128
#define NH 8
#define HD 16
#define NET 5
#define ATILE 64

// ---- scratch (device globals; no allocation allowed) ----
__device__ float  gQ[NN * DIM];
__device__ __half gKtH[NET * NN * DIM];  // K transformed, fp16 (64MB)
__device__ __half gVH[NN * DIM];         // V, fp16 (12.8MB)
__device__ float  gAgg[NN * DIM];
__device__ float  gHid[NN * DIM];
__device__ float  gF1[NN * 4 * DIM];
__device__ int    gEid[NE];              // packed: (etype<<20) | src
__device__ int    gCnt[NN];
__device__ int    gCur[NN];
__device__ int    gRow[NN + 1];
__device__ int    gBlkSum[64];
__device__ int    gBlkOff[64];

// ---------------------------------------------------------------------------
__global__ void init_kernel(int N) {
    int i = blockIdx.x * blockDim.x + threadIdx.x;
    if (i < N) { gCnt[i] = 0; gCur[i] = 0; }
}

// ---------------------------------------------------------------------------
// per-node-type QKV + per-edge-type K transform (all 5 types precomputed)
// ---------------------------------------------------------------------------
__global__ void qkv_kt_kernel(const float* __restrict__ x,
                              const int* __restrict__ node_type,
                              const float* __restrict__ WQ,
                              const float* __restrict__ WK,
                              const float* __restrict__ WV,
                              const float* __restrict__ We) {
    int n = blockIdx.x;
    int tid = threadIdx.x;
    __shared__ float xs[DIM];
    __shared__ float ks[DIM];
    xs[tid] = x[n * DIM + tid];
    __syncthreads();
    int t = node_type[n];
    int h = tid >> 4, f = tid & 15;
    const float* xr = xs + h * HD;
    int base = ((t * NH + h) * HD) * HD + f;
    float q = 0.f, k = 0.f, v = 0.f;
#pragma unroll
    for (int d = 0; d < HD; d++) {
        float xv = xr[d];
        q = fmaf(xv, WQ[base + d * HD], q);
        k = fmaf(xv, WK[base + d * HD], k);
        v = fmaf(xv, WV[base + d * HD], v);
    }
    gQ[n * DIM + tid] = q;
    gVH[n * DIM + tid] = __float2half(v);
    ks[tid] = k;
    __syncthreads();
    const float* kr = ks + h * HD;
#pragma unroll
    for (int et = 0; et < NET; et++) {
        const float* w = We + ((et * NH + h) * HD) * HD + f;
        float acc = 0.f;
#pragma unroll
        for (int d = 0; d < HD; d++) acc = fmaf(kr[d], w[d * HD], acc);
        gKtH[(et * NN + n) * DIM + tid] = __float2half(acc);
    }
}

// ---------------------------------------------------------------------------
// CSR build
// ---------------------------------------------------------------------------
__global__ void hist_kernel(const int* __restrict__ ei, int E) {
    int e = blockIdx.x * blockDim.x + threadIdx.x;
    if (e < E) atomicAdd(&gCnt[ei[E + e]], 1);
}

__global__ void scan_local_kernel(int N) {
    __shared__ int sh[1024];
    int t = threadIdx.x;
    int i = blockIdx.x * 1024 + t;
    int v = (i < N) ? gCnt[i] : 0;
    sh[t] = v;
    __syncthreads();
#pragma unroll
    for (int off = 1; off < 1024; off <<= 1) {
        int add = (t >= off) ? sh[t - off] : 0;
        __syncthreads();
        sh[t] += add;
        __syncthreads();
    }
    if (i < N) gRow[i] = sh[t] - v;
    if (t == 1023) gBlkSum[blockIdx.x] = sh[1023];
}

__global__ void scan_block_kernel(int nblk) {
    __shared__ int sh[64];
    int t = threadIdx.x;
    int v = (t < nblk) ? gBlkSum[t] : 0;
    sh[t] = v;
    __syncthreads();
#pragma unroll
    for (int off = 1; off < 64; off <<= 1) {
        int add = (t >= off) ? sh[t - off] : 0;
        __syncthreads();
        sh[t] += add;
        __syncthreads();
    }
    gBlkOff[t] = sh[t] - v;
}

__global__ void scan_add_kernel(int N, int E) {
    int i = blockIdx.x * blockDim.x + threadIdx.x;
    if (i < N) gRow[i] += gBlkOff[i >> 10];
    if (i == 0) gRow[N] = E;
}

// pack (etype<<20 | src) so attention does ONE indexed load per edge
__global__ void fill_kernel(const int* __restrict__ ei,
                            const int* __restrict__ etype, int E) {
    int e = blockIdx.x * blockDim.x + threadIdx.x;
    if (e < E) {
        int dst = ei[E + e];
        int p = atomicAdd(&gCur[dst], 1);
        gEid[gRow[dst] + p] = (etype[e] << 20) | ei[e];
    }
}

// ---------------------------------------------------------------------------
// fused attention: per-dst block (128 thr), tile softmax, V stashed in smem.
// Phase 1 gathers Kt AND V together (2x MLP), V -> smem; phase 3 is LDS-only.
// ---------------------------------------------------------------------------
__global__ void attn_kernel(const float* __restrict__ mu, int E) {
    int n = blockIdx.x;
    int tid = threadIdx.x;
    int h = tid >> 4, f = tid & 15;
    __shared__ int s_pk[ATILE];
    __shared__ float s_sc[ATILE][9];     // [edge][head], conflict-light
    __shared__ __half s_v[ATILE][DIM];   // V tile stash (16KB)
    float q = gQ[n * DIM + tid];
    float muh[NET];
#pragma unroll
    for (int et = 0; et < NET; et++) muh[et] = mu[h * NET + et] * 0.25f;

    float m = -3.402823466e38f, den = 0.f, acc = 0.f;
    int row0 = gRow[n], row1 = gRow[n + 1];
    for (int cs = row0; cs < row1; cs += ATILE) {
        int c = min(ATILE, row1 - cs);
        if (tid < c) s_pk[tid] = gEid[cs + tid];
        __syncthreads();

        // ---- phase 1: scores + V stash (kt & v gathers co-issued) ----
        for (int j = 0; j < c; j += 2) {
            int pk0 = s_pk[j];
            int src0 = pk0 & 0xFFFFF, et0 = pk0 >> 20;
            __half kt0 = gKtH[(et0 * NN + src0) * DIM + tid];
            __half vv0 = gVH[src0 * DIM + tid];
            int have1 = (j + 1 < c);
            int pk1 = s_pk[have1 ? j + 1 : j];
            int src1 = pk1 & 0xFFFFF, et1 = pk1 >> 20;
            __half kt1 = gKtH[(et1 * NN + src1) * DIM + tid];
            __half vv1 = gVH[src1 * DIM + tid];

            s_v[j][tid] = vv0;
            float s0 = q * __half2float(kt0);
            s0 += __shfl_xor_sync(0xffffffffu, s0, 1);
            s0 += __shfl_xor_sync(0xffffffffu, s0, 2);
            s0 += __shfl_xor_sync(0xffffffffu, s0, 4);
            s0 += __shfl_xor_sync(0xffffffffu, s0, 8);
            if (f == 0) s_sc[j][h] = s0 * muh[et0];

            if (have1) {
                s_v[j + 1][tid] = vv1;
                float s1 = q * __half2float(kt1);
                s1 += __shfl_xor_sync(0xffffffffu, s1, 1);
                s1 += __shfl_xor_sync(0xffffffffu, s1, 2);
                s1 += __shfl_xor_sync(0xffffffffu, s1, 4);
                s1 += __shfl_xor_sync(0xffffffffu, s1, 8);
                if (f == 0) s_sc[j + 1][h] = s1 * muh[et1];
            }
        }
        __syncwarp();

        // ---- phase 2: per-head tile max, exp weights, denominator ----
        float tmax = -3.402823466e38f;
        for (int j = f; j < c; j += 16) tmax = fmaxf(tmax, s_sc[j][h]);
        tmax = fmaxf(tmax, __shfl_xor_sync(0xffffffffu, tmax, 1));
        tmax = fmaxf(tmax, __shfl_xor_sync(0xffffffffu, tmax, 2));
        tmax = fmaxf(tmax, __shfl_xor_sync(0xffffffffu, tmax, 4));
        tmax = fmaxf(tmax, __shfl_xor_sync(0xffffffffu, tmax, 8));
        float newm = fmaxf(m, tmax);
        float scale = __expf(m - newm);
        float dtile = 0.f;
        for (int j = f; j < c; j += 16) {
            float w = __expf(s_sc[j][h] - newm);
            s_sc[j][h] = w;
            dtile += w;
        }
        dtile += __shfl_xor_sync(0xffffffffu, dtile, 1);
        dtile += __shfl_xor_sync(0xffffffffu, dtile, 2);
        dtile += __shfl_xor_sync(0xffffffffu, dtile, 4);
        dtile += __shfl_xor_sync(0xffffffffu, dtile, 8);
        den = den * scale + dtile;
        acc *= scale;
        m = newm;
        __syncwarp();

        // ---- phase 3: weighted V accumulation from smem ----
        for (int j = 0; j < c; j++) {
            acc = fmaf(s_sc[j][h], __half2float(s_v[j][tid]), acc);
        }
        __syncthreads();
    }
    gAgg[n * DIM + tid] = acc / (den + 1e-10f);
}

// ---------------------------------------------------------------------------
// oproj: tiled SIMT GEMM (M x 128 x 128) + bias + residual + LN1 -> gHid
// ---------------------------------------------------------------------------
__global__ void oproj_ln1_kernel(const float* __restrict__ x,
                                 const float* __restrict__ Wo,
                                 const float* __restrict__ bo,
                                 const float* __restrict__ g1,
                                 const float* __restrict__ bb1, int M) {
    __shared__ float As[32][132];
    __shared__ float Bs[32][132];
    int tid = threadIdx.x;
    int tx = tid & 15, ty = tid >> 4;
    int m0 = blockIdx.y * 128;
    float acc[8][8];
#pragma unroll
    for (int i = 0; i < 8; i++)
#pragma unroll
        for (int j = 0; j < 8; j++) acc[i][j] = 0.f;

    for (int k0 = 0; k0 < 128; k0 += 32) {
#pragma unroll
        for (int l = tid; l < 1024; l += 256) {
            int m = l >> 3;
            int kq = (l & 7) << 2;
            int gm = m0 + m; if (gm >= M) gm = M - 1;
            float4 a = *(const float4*)(&gAgg[gm * 128 + k0 + kq]);
            As[kq][m] = a.x; As[kq + 1][m] = a.y; As[kq + 2][m] = a.z; As[kq + 3][m] = a.w;
        }
#pragma unroll
        for (int l = tid; l < 1024; l += 256) {
            int k = l >> 5;
            int nq = (l & 31) << 2;
            *(float4*)&Bs[k][nq] = *(const float4*)(&Wo[(k0 + k) * 128 + nq]);
        }
        __syncthreads();
#pragma unroll
        for (int k = 0; k < 32; k++) {
            float a[8], b[8];
            *(float4*)&a[0] = *(const float4*)&As[k][ty * 8];
            *(float4*)&a[4] = *(const float4*)&As[k][ty * 8 + 4];
            *(float4*)&b[0] = *(const float4*)&Bs[k][tx * 8];
            *(float4*)&b[4] = *(const float4*)&Bs[k][tx * 8 + 4];
#pragma unroll
            for (int i = 0; i < 8; i++)
#pragma unroll
                for (int j = 0; j < 8; j++) acc[i][j] = fmaf(a[i], b[j], acc[i][j]);
        }
        __syncthreads();
    }
    float bl[8], g1l[8], b1l[8];
#pragma unroll
    for (int j = 0; j < 8; j++) {
        int gn = tx * 8 + j;
        bl[j] = bo[gn]; g1l[j] = g1[gn]; b1l[j] = bb1[gn];
    }
#pragma unroll
    for (int i = 0; i < 8; i++) {
        int gm = m0 + ty * 8 + i;
        int gms = (gm < M) ? gm : (M - 1);
        float yv[8];
        float ssum = 0.f;
#pragma unroll
        for (int j = 0; j < 8; j++) {
            yv[j] = acc[i][j] + bl[j] + x[gms * 128 + tx * 8 + j];
            ssum += yv[j];
        }
        ssum += __shfl_xor_sync(0xffffffffu, ssum, 1);
        ssum += __shfl_xor_sync(0xffffffffu, ssum, 2);
        ssum += __shfl_xor_sync(0xffffffffu, ssum, 4);
        ssum += __shfl_xor_sync(0xffffffffu, ssum, 8);
        float mean = ssum * (1.f / DIM);
        float s2 = 0.f;
#pragma unroll
        for (int j = 0; j < 8; j++) {
            float dv = yv[j] - mean;
            s2 = fmaf(dv, dv, s2);
        }
        s2 += __shfl_xor_sync(0xffffffffu, s2, 1);
        s2 += __shfl_xor_sync(0xffffffffu, s2, 2);
        s2 += __shfl_xor_sync(0xffffffffu, s2, 4);
        s2 += __shfl_xor_sync(0xffffffffu, s2, 8);
        float rstd = rsqrtf(s2 * (1.f / DIM) + 1e-5f);
        if (gm < M) {
            float o[8];
#pragma unroll
            for (int j = 0; j < 8; j++)
                o[j] = (yv[j] - mean) * rstd * g1l[j] + b1l[j];
            *(float4*)&gHid[gm * 128 + tx * 8]     = *(float4*)&o[0];
            *(float4*)&gHid[gm * 128 + tx * 8 + 4] = *(float4*)&o[4];
        }
    }
}

// ---------------------------------------------------------------------------
// tf32 tensor-core machinery
// ---------------------------------------------------------------------------
__device__ __forceinline__ unsigned f2tf(float f) {
    unsigned r;
    asm("cvt.rna.tf32.f32 %0, %1;" : "=r"(r) : "f"(f));
    return r;
}
__device__ __forceinline__ void mma_tf32(float* c, const unsigned* a, const unsigned* b) {
    asm volatile(
        "mma.sync.aligned.m16n8k8.row.col.f32.tf32.tf32.f32 "
        "{%0,%1,%2,%3},{%4,%5,%6,%7},{%8,%9},{%0,%1,%2,%3};"
        : "+f"(c[0]), "+f"(c[1]), "+f"(c[2]), "+f"(c[3])
        : "r"(a[0]), "r"(a[1]), "r"(a[2]), "r"(a[3]), "r"(b[0]), "r"(b[1]));
}

// ---------------------------------------------------------------------------
// FFN1: gF1[M,512] = gelu(gHid[M,128] @ W1 + b1)
// ---------------------------------------------------------------------------
__global__ void ffn1_tc(const float* __restrict__ W1,
                        const float* __restrict__ b1v, int M) {
    __shared__ unsigned As[128][36];
    __shared__ unsigned Bs[32][132];
    int tid = threadIdx.x, lane = tid & 31, wid = tid >> 5;
    int wy = (wid & 3) * 32, wx = (wid >> 2) * 32;
    int m0 = blockIdx.y * 128, n0 = blockIdx.x * 128;
    int r = lane >> 2, t = lane & 3;
    float c[2][4][4];
#pragma unroll
    for (int i = 0; i < 2; i++)
#pragma unroll
        for (int j = 0; j < 4; j++)
#pragma unroll
            for (int q = 0; q < 4; q++) c[i][j][q] = 0.f;

    for (int k0 = 0; k0 < 128; k0 += 32) {
#pragma unroll
        for (int l = tid; l < 1024; l += 512) {
            int m = l >> 3, kq = (l & 7) << 2;
            int gm = m0 + m; if (gm >= M) gm = M - 1;
            float4 a = *(const float4*)(&gHid[gm * 128 + k0 + kq]);
            As[m][kq] = f2tf(a.x); As[m][kq + 1] = f2tf(a.y);
            As[m][kq + 2] = f2tf(a.z); As[m][kq + 3] = f2tf(a.w);
        }
#pragma unroll
        for (int l = tid; l < 1024; l += 512) {
            int k = l >> 5, nq = (l & 31) << 2;
            float4 b = *(const float4*)(&W1[(k0 + k) * 512 + n0 + nq]);
            Bs[k][nq] = f2tf(b.x); Bs[k][nq + 1] = f2tf(b.y);
            Bs[k][nq + 2] = f2tf(b.z); Bs[k][nq + 3] = f2tf(b.w);
        }
        __syncthreads();
#pragma unroll
        for (int kk = 0; kk < 32; kk += 8) {
            unsigned af[2][4], bf[4][2];
#pragma unroll
            for (int i = 0; i < 2; i++) {
                af[i][0] = As[wy + i * 16 + r][kk + t];
                af[i][1] = As[wy + i * 16 + r + 8][kk + t];
                af[i][2] = As[wy + i * 16 + r][kk + t + 4];
                af[i][3] = As[wy + i * 16 + r + 8][kk + t + 4];
            }
#pragma unroll
            for (int j = 0; j < 4; j++) {
                bf[j][0] = Bs[kk + t][wx + j * 8 + r];
                bf[j][1] = Bs[kk + t + 4][wx + j * 8 + r];
            }
#pragma unroll
            for (int i = 0; i < 2; i++)
#pragma unroll
                for (int j = 0; j < 4; j++) mma_tf32(c[i][j], af[i], bf[j]);
        }
        __syncthreads();
    }
#pragma unroll
    for (int i = 0; i < 2; i++) {
        int row = m0 + wy + i * 16 + r;
        int row2 = row + 8;
#pragma unroll
        for (int j = 0; j < 4; j++) {
            int col = n0 + wx + j * 8 + 2 * t;
            float bc0 = b1v[col], bc1 = b1v[col + 1];
            if (row < M) {
                float v0 = c[i][j][0] + bc0;
                float v1 = c[i][j][1] + bc1;
                v0 = 0.5f * v0 * (1.f + erff(v0 * 0.7071067811865476f));
                v1 = 0.5f * v1 * (1.f + erff(v1 * 0.7071067811865476f));
                *(float2*)&gF1[row * 512 + col] = make_float2(v0, v1);
            }
            if (row2 < M) {
                float v0 = c[i][j][2] + bc0;
                float v1 = c[i][j][3] + bc1;
                v0 = 0.5f * v0 * (1.f + erff(v0 * 0.7071067811865476f));
                v1 = 0.5f * v1 * (1.f + erff(v1 * 0.7071067811865476f));
                *(float2*)&gF1[row2 * 512 + col] = make_float2(v0, v1);
            }
        }
    }
}

// ---------------------------------------------------------------------------
// FFN2: out = LN2(gHid + gF1[M,512] @ W2 + b2), 512 thr, fused LN epilogue
// ---------------------------------------------------------------------------
__global__ void ffn2_tc_ln2(const float* __restrict__ W2,
                            const float* __restrict__ b2v,
                            const float* __restrict__ g2,
                            const float* __restrict__ bb2,
                            float* __restrict__ out, int M) {
    __shared__ unsigned As[128][36];
    __shared__ unsigned Bs[32][132];
    __shared__ float rs[4][128];
    __shared__ float rq[4][128];
    int tid = threadIdx.x, lane = tid & 31, wid = tid >> 5;
    int wy = (wid & 3) * 32, wxg = wid >> 2;
    int wx = wxg * 32;
    int m0 = blockIdx.y * 128;
    int r = lane >> 2, t = lane & 3;
    float c[2][4][4];
#pragma unroll
    for (int i = 0; i < 2; i++)
#pragma unroll
        for (int j = 0; j < 4; j++)
#pragma unroll
            for (int q = 0; q < 4; q++) c[i][j][q] = 0.f;

    for (int k0 = 0; k0 < 512; k0 += 32) {
#pragma unroll
        for (int l = tid; l < 1024; l += 512) {
            int m = l >> 3, kq = (l & 7) << 2;
            int gm = m0 + m; if (gm >= M) gm = M - 1;
            float4 a = *(const float4*)(&gF1[gm * 512 + k0 + kq]);
            As[m][kq] = f2tf(a.x); As[m][kq + 1] = f2tf(a.y);
            As[m][kq + 2] = f2tf(a.z); As[m][kq + 3] = f2tf(a.w);
        }
#pragma unroll
        for (int l = tid; l < 1024; l += 512) {
            int k = l >> 5, nq = (l & 31) << 2;
            float4 b = *(const float4*)(&W2[(k0 + k) * 128 + nq]);
            Bs[k][nq] = f2tf(b.x); Bs[k][nq + 1] = f2tf(b.y);
            Bs[k][nq + 2] = f2tf(b.z); Bs[k][nq + 3] = f2tf(b.w);
        }
        __syncthreads();
#pragma unroll
        for (int kk = 0; kk < 32; kk += 8) {
            unsigned af[2][4], bf[4][2];
#pragma unroll
            for (int i = 0; i < 2; i++) {
                af[i][0] = As[wy + i * 16 + r][kk + t];
                af[i][1] = As[wy + i * 16 + r + 8][kk + t];
                af[i][2] = As[wy + i * 16 + r][kk + t + 4];
                af[i][3] = As[wy + i * 16 + r + 8][kk + t + 4];
            }
#pragma unroll
            for (int j = 0; j < 4; j++) {
                bf[j][0] = Bs[kk + t][wx + j * 8 + r];
                bf[j][1] = Bs[kk + t + 4][wx + j * 8 + r];
            }
#pragma unroll
            for (int i = 0; i < 2; i++)
#pragma unroll
                for (int j = 0; j < 4; j++) mma_tf32(c[i][j], af[i], bf[j]);
        }
        __syncthreads();
    }

    float sum[2][2] = {{0.f, 0.f}, {0.f, 0.f}};
    float sq2[2][2] = {{0.f, 0.f}, {0.f, 0.f}};
#pragma unroll
    for (int i = 0; i < 2; i++) {
        int row = m0 + wy + i * 16 + r;
        int rowc  = (row < M) ? row : (M - 1);
        int row2c = (row + 8 < M) ? (row + 8) : (M - 1);
#pragma unroll
        for (int j = 0; j < 4; j++) {
            int col = wx + j * 8 + 2 * t;
            float bc0 = b2v[col], bc1 = b2v[col + 1];
            float2 h0 = *(const float2*)&gHid[rowc * 128 + col];
            float2 h1 = *(const float2*)&gHid[row2c * 128 + col];
            c[i][j][0] += bc0 + h0.x;
            c[i][j][1] += bc1 + h0.y;
            c[i][j][2] += bc0 + h1.x;
            c[i][j][3] += bc1 + h1.y;
            sum[i][0] += c[i][j][0] + c[i][j][1];
            sum[i][1] += c[i][j][2] + c[i][j][3];
            sq2[i][0] = fmaf(c[i][j][0], c[i][j][0], fmaf(c[i][j][1], c[i][j][1], sq2[i][0]));
            sq2[i][1] = fmaf(c[i][j][2], c[i][j][2], fmaf(c[i][j][3], c[i][j][3], sq2[i][1]));
        }
    }
#pragma unroll
    for (int i = 0; i < 2; i++) {
#pragma unroll
        for (int hl = 0; hl < 2; hl++) {
            sum[i][hl] += __shfl_xor_sync(0xffffffffu, sum[i][hl], 1);
            sum[i][hl] += __shfl_xor_sync(0xffffffffu, sum[i][hl], 2);
            sq2[i][hl] += __shfl_xor_sync(0xffffffffu, sq2[i][hl], 1);
            sq2[i][hl] += __shfl_xor_sync(0xffffffffu, sq2[i][hl], 2);
        }
    }
    if (t == 0) {
#pragma unroll
        for (int i = 0; i < 2; i++) {
            rs[wxg][wy + i * 16 + r]     = sum[i][0];
            rs[wxg][wy + i * 16 + r + 8] = sum[i][1];
            rq[wxg][wy + i * 16 + r]     = sq2[i][0];
            rq[wxg][wy + i * 16 + r + 8] = sq2[i][1];
        }
    }
    __syncthreads();
#pragma unroll
    for (int i = 0; i < 2; i++) {
#pragma unroll
        for (int hl = 0; hl < 2; hl++) {
            int rl = wy + i * 16 + r + hl * 8;
            int row = m0 + rl;
            float s  = rs[0][rl] + rs[1][rl] + rs[2][rl] + rs[3][rl];
            float s2 = rq[0][rl] + rq[1][rl] + rq[2][rl] + rq[3][rl];
            float mean = s * (1.f / DIM);
            float var = s2 * (1.f / DIM) - mean * mean;
            float rstd = rsqrtf(var + 1e-5f);
            if (row < M) {
#pragma unroll
                for (int j = 0; j < 4; j++) {
                    int col = wx + j * 8 + 2 * t;
                    float y0 = c[i][j][hl * 2 + 0];
                    float y1 = c[i][j][hl * 2 + 1];
                    float o0 = (y0 - mean) * rstd * g2[col] + bb2[col];
                    float o1 = (y1 - mean) * rstd * g2[col + 1] + bb2[col + 1];
                    *(float2*)&out[row * 128 + col] = make_float2(o0, o1);
                }
            }
        }
    }
}

// ---------------------------------------------------------------------------
extern "C" void kernel_launch(void* const* d_in, const int* in_sizes, int n_in,
                              void* d_out, int out_size) {
    const float* x     = (const float*)d_in[0];
    const int*   ei    = (const int*)d_in[1];
    const int*   etype = (const int*)d_in[2];
    const int*   ntype = (const int*)d_in[3];
    const float* WQ    = (const float*)d_in[4];
    const float* WK    = (const float*)d_in[5];
    const float* WV    = (const float*)d_in[6];
    const float* We    = (const float*)d_in[7];
    const float* mu    = (const float*)d_in[8];
    const float* Wo    = (const float*)d_in[9];
    const float* bo    = (const float*)d_in[10];
    const float* ln1g  = (const float*)d_in[11];
    const float* ln1b  = (const float*)d_in[12];
    const float* W1    = (const float*)d_in[13];
    const float* b1    = (const float*)d_in[14];
    const float* W2    = (const float*)d_in[15];
    const float* b2    = (const float*)d_in[16];
    const float* ln2g  = (const float*)d_in[17];
    const float* ln2b  = (const float*)d_in[18];

    int N = in_sizes[0] / DIM;   // 50000
    int E = in_sizes[1] / 2;     // 800000
    int nblk = (N + 1023) / 1024;
    int mtiles = (N + 127) / 128;

    init_kernel<<<(N + 255) / 256, 256>>>(N);
    qkv_kt_kernel<<<N, 128>>>(x, ntype, WQ, WK, WV, We);
    hist_kernel<<<(E + 255) / 256, 256>>>(ei, E);
    scan_local_kernel<<<nblk, 1024>>>(N);
    scan_block_kernel<<<1, 64>>>(nblk);
    scan_add_kernel<<<(N + 255) / 256, 256>>>(N, E);
    fill_kernel<<<(E + 255) / 256, 256>>>(ei, etype, E);
    attn_kernel<<<N, 128>>>(mu, E);
    oproj_ln1_kernel<<<dim3(1, mtiles), 256>>>(x, Wo, bo, ln1g, ln1b, N);
    ffn1_tc<<<dim3(4, mtiles), 512>>>(W1, b1, N);
    ffn2_tc_ln2<<<dim3(1, mtiles), 512>>>(W2, b2, ln2g, ln2b, (float*)d_out, N);
}

// round 8
// speedup vs baseline: 1.0205x; 1.0205x over previous
#include <cuda_runtime.h>
#include <cuda_fp16.h>
#include <math.h>

#define NN 50000
#define NE 800000
#define DIM 128
#define NH 8
#define HD 16
#define NET 5

// ---- scratch (device globals; no allocation allowed) ----
__device__ float  gQ[NN * DIM];
__device__ __half gKtH[NET * NN * DIM];  // K transformed, fp16 (64MB)
__device__ __half gVH[NN * DIM];         // V, fp16 (12.8MB)
__device__ float  gAgg[NN * DIM];
__device__ float  gHid[NN * DIM];
__device__ int    gEid[NE];              // packed: (etype<<20) | src
__device__ int    gCnt[NN];
__device__ int    gCur[NN];
__device__ int    gRow[NN + 1];
__device__ int    gBlkSum[64];
__device__ int    gBlkOff[64];

// ---------------------------------------------------------------------------
__global__ void init_kernel(int N) {
    int i = blockIdx.x * blockDim.x + threadIdx.x;
    if (i < N) { gCnt[i] = 0; gCur[i] = 0; }
}

// ---------------------------------------------------------------------------
// per-node-type QKV + per-edge-type K transform (all 5 types precomputed)
// ---------------------------------------------------------------------------
__global__ void qkv_kt_kernel(const float* __restrict__ x,
                              const int* __restrict__ node_type,
                              const float* __restrict__ WQ,
                              const float* __restrict__ WK,
                              const float* __restrict__ WV,
                              const float* __restrict__ We) {
    int n = blockIdx.x;
    int tid = threadIdx.x;
    __shared__ float xs[DIM];
    __shared__ float ks[DIM];
    xs[tid] = x[n * DIM + tid];
    __syncthreads();
    int t = node_type[n];
    int h = tid >> 4, f = tid & 15;
    const float* xr = xs + h * HD;
    int base = ((t * NH + h) * HD) * HD + f;
    float q = 0.f, k = 0.f, v = 0.f;
#pragma unroll
    for (int d = 0; d < HD; d++) {
        float xv = xr[d];
        q = fmaf(xv, WQ[base + d * HD], q);
        k = fmaf(xv, WK[base + d * HD], k);
        v = fmaf(xv, WV[base + d * HD], v);
    }
    gQ[n * DIM + tid] = q;
    gVH[n * DIM + tid] = __float2half(v);
    ks[tid] = k;
    __syncthreads();
    const float* kr = ks + h * HD;
#pragma unroll
    for (int et = 0; et < NET; et++) {
        const float* w = We + ((et * NH + h) * HD) * HD + f;
        float acc = 0.f;
#pragma unroll
        for (int d = 0; d < HD; d++) acc = fmaf(kr[d], w[d * HD], acc);
        gKtH[(et * NN + n) * DIM + tid] = __float2half(acc);
    }
}

// ---------------------------------------------------------------------------
// CSR build
// ---------------------------------------------------------------------------
__global__ void hist_kernel(const int* __restrict__ ei, int E) {
    int e = blockIdx.x * blockDim.x + threadIdx.x;
    if (e < E) atomicAdd(&gCnt[ei[E + e]], 1);
}

__global__ void scan_local_kernel(int N) {
    __shared__ int sh[1024];
    int t = threadIdx.x;
    int i = blockIdx.x * 1024 + t;
    int v = (i < N) ? gCnt[i] : 0;
    sh[t] = v;
    __syncthreads();
#pragma unroll
    for (int off = 1; off < 1024; off <<= 1) {
        int add = (t >= off) ? sh[t - off] : 0;
        __syncthreads();
        sh[t] += add;
        __syncthreads();
    }
    if (i < N) gRow[i] = sh[t] - v;
    if (t == 1023) gBlkSum[blockIdx.x] = sh[1023];
}

__global__ void scan_block_kernel(int nblk) {
    __shared__ int sh[64];
    int t = threadIdx.x;
    int v = (t < nblk) ? gBlkSum[t] : 0;
    sh[t] = v;
    __syncthreads();
#pragma unroll
    for (int off = 1; off < 64; off <<= 1) {
        int add = (t >= off) ? sh[t - off] : 0;
        __syncthreads();
        sh[t] += add;
        __syncthreads();
    }
    gBlkOff[t] = sh[t] - v;
}

__global__ void scan_add_kernel(int N, int E) {
    int i = blockIdx.x * blockDim.x + threadIdx.x;
    if (i < N) gRow[i] += gBlkOff[i >> 10];
    if (i == 0) gRow[N] = E;
}

// pack (etype<<20 | src): attention does ONE indexed load per edge
__global__ void fill_kernel(const int* __restrict__ ei,
                            const int* __restrict__ etype, int E) {
    int e = blockIdx.x * blockDim.x + threadIdx.x;
    if (e < E) {
        int dst = ei[E + e];
        int p = atomicAdd(&gCur[dst], 1);
        gEid[gRow[dst] + p] = (etype[e] << 20) | ei[e];
    }
}

// ---------------------------------------------------------------------------
// fused attention (R6 structure): per-dst block (128 thr), 3-phase tile
// softmax, no atomics, packed edge records.
// ---------------------------------------------------------------------------
__global__ void attn_kernel(const float* __restrict__ mu, int E) {
    int n = blockIdx.x;
    int tid = threadIdx.x;
    int h = tid >> 4, f = tid & 15;
    __shared__ int s_pk[128];
    __shared__ float s_sc[128][9];   // [edge][head]
    float q = gQ[n * DIM + tid];
    float muh[NET];
#pragma unroll
    for (int et = 0; et < NET; et++) muh[et] = mu[h * NET + et] * 0.25f;

    float m = -3.402823466e38f, den = 0.f, acc = 0.f;
    int row0 = gRow[n], row1 = gRow[n + 1];
    for (int cs = row0; cs < row1; cs += 128) {
        int c = min(128, row1 - cs);
        if (tid < c) s_pk[tid] = gEid[cs + tid];
        __syncthreads();

        // phase 1: scores
        for (int j = 0; j < c; j++) {
            int pk = s_pk[j];
            int src = pk & 0xFFFFF, et = pk >> 20;
            float kt = __half2float(gKtH[(et * NN + src) * DIM + tid]);
            float s = q * kt;
            s += __shfl_xor_sync(0xffffffffu, s, 1);
            s += __shfl_xor_sync(0xffffffffu, s, 2);
            s += __shfl_xor_sync(0xffffffffu, s, 4);
            s += __shfl_xor_sync(0xffffffffu, s, 8);
            if (f == 0) s_sc[j][h] = s * muh[et];
        }
        __syncwarp();

        // phase 2: per-head tile max, exp weights, denominator
        float tmax = -3.402823466e38f;
        for (int j = f; j < c; j += 16) tmax = fmaxf(tmax, s_sc[j][h]);
        tmax = fmaxf(tmax, __shfl_xor_sync(0xffffffffu, tmax, 1));
        tmax = fmaxf(tmax, __shfl_xor_sync(0xffffffffu, tmax, 2));
        tmax = fmaxf(tmax, __shfl_xor_sync(0xffffffffu, tmax, 4));
        tmax = fmaxf(tmax, __shfl_xor_sync(0xffffffffu, tmax, 8));
        float newm = fmaxf(m, tmax);
        float scale = __expf(m - newm);
        float dtile = 0.f;
        for (int j = f; j < c; j += 16) {
            float w = __expf(s_sc[j][h] - newm);
            s_sc[j][h] = w;
            dtile += w;
        }
        dtile += __shfl_xor_sync(0xffffffffu, dtile, 1);
        dtile += __shfl_xor_sync(0xffffffffu, dtile, 2);
        dtile += __shfl_xor_sync(0xffffffffu, dtile, 4);
        dtile += __shfl_xor_sync(0xffffffffu, dtile, 8);
        den = den * scale + dtile;
        acc *= scale;
        m = newm;
        __syncwarp();

        // phase 3: weighted V accumulation
        for (int j = 0; j < c; j++) {
            float v = __half2float(gVH[(s_pk[j] & 0xFFFFF) * DIM + tid]);
            acc = fmaf(s_sc[j][h], v, acc);
        }
        __syncthreads();
    }
    gAgg[n * DIM + tid] = acc / (den + 1e-10f);
}

// ---------------------------------------------------------------------------
// tf32 tensor-core machinery
// ---------------------------------------------------------------------------
__device__ __forceinline__ unsigned f2tf(float f) {
    unsigned r;
    asm("cvt.rna.tf32.f32 %0, %1;" : "=r"(r) : "f"(f));
    return r;
}
__device__ __forceinline__ void mma_tf32(float* c, const unsigned* a, const unsigned* b) {
    asm volatile(
        "mma.sync.aligned.m16n8k8.row.col.f32.tf32.tf32.f32 "
        "{%0,%1,%2,%3},{%4,%5,%6,%7},{%8,%9},{%0,%1,%2,%3};"
        : "+f"(c[0]), "+f"(c[1]), "+f"(c[2]), "+f"(c[3])
        : "r"(a[0]), "r"(a[1]), "r"(a[2]), "r"(a[3]), "r"(b[0]), "r"(b[1]));
}

// ---------------------------------------------------------------------------
// oproj tf32: gHid = LN1(x + gAgg @ Wo + bo); 512 thr, 128-row tiles, K=128
// ---------------------------------------------------------------------------
__global__ void oproj_tc_ln1(const float* __restrict__ x,
                             const float* __restrict__ Wo,
                             const float* __restrict__ bo,
                             const float* __restrict__ g1,
                             const float* __restrict__ bb1, int M) {
    __shared__ unsigned As[128][36];
    __shared__ unsigned Bs[32][132];
    __shared__ float rs[4][128];
    __shared__ float rq[4][128];
    int tid = threadIdx.x, lane = tid & 31, wid = tid >> 5;
    int wy = (wid & 3) * 32, wxg = wid >> 2;
    int wx = wxg * 32;
    int m0 = blockIdx.y * 128;
    int r = lane >> 2, t = lane & 3;
    float c[2][4][4];
#pragma unroll
    for (int i = 0; i < 2; i++)
#pragma unroll
        for (int j = 0; j < 4; j++)
#pragma unroll
            for (int q = 0; q < 4; q++) c[i][j][q] = 0.f;

    for (int k0 = 0; k0 < 128; k0 += 32) {
#pragma unroll
        for (int l = tid; l < 1024; l += 512) {
            int m = l >> 3, kq = (l & 7) << 2;
            int gm = m0 + m; if (gm >= M) gm = M - 1;
            float4 a = *(const float4*)(&gAgg[gm * 128 + k0 + kq]);
            As[m][kq] = f2tf(a.x); As[m][kq + 1] = f2tf(a.y);
            As[m][kq + 2] = f2tf(a.z); As[m][kq + 3] = f2tf(a.w);
        }
#pragma unroll
        for (int l = tid; l < 1024; l += 512) {
            int k = l >> 5, nq = (l & 31) << 2;
            float4 b = *(const float4*)(&Wo[(k0 + k) * 128 + nq]);
            Bs[k][nq] = f2tf(b.x); Bs[k][nq + 1] = f2tf(b.y);
            Bs[k][nq + 2] = f2tf(b.z); Bs[k][nq + 3] = f2tf(b.w);
        }
        __syncthreads();
#pragma unroll
        for (int kk = 0; kk < 32; kk += 8) {
            unsigned af[2][4], bf[4][2];
#pragma unroll
            for (int i = 0; i < 2; i++) {
                af[i][0] = As[wy + i * 16 + r][kk + t];
                af[i][1] = As[wy + i * 16 + r + 8][kk + t];
                af[i][2] = As[wy + i * 16 + r][kk + t + 4];
                af[i][3] = As[wy + i * 16 + r + 8][kk + t + 4];
            }
#pragma unroll
            for (int j = 0; j < 4; j++) {
                bf[j][0] = Bs[kk + t][wx + j * 8 + r];
                bf[j][1] = Bs[kk + t + 4][wx + j * 8 + r];
            }
#pragma unroll
            for (int i = 0; i < 2; i++)
#pragma unroll
                for (int j = 0; j < 4; j++) mma_tf32(c[i][j], af[i], bf[j]);
        }
        __syncthreads();
    }

    // epilogue: y = c + bo + x (residual); LN1 -> gHid
    float sum[2][2] = {{0.f, 0.f}, {0.f, 0.f}};
    float sq2[2][2] = {{0.f, 0.f}, {0.f, 0.f}};
#pragma unroll
    for (int i = 0; i < 2; i++) {
        int row = m0 + wy + i * 16 + r;
        int rowc  = (row < M) ? row : (M - 1);
        int row2c = (row + 8 < M) ? (row + 8) : (M - 1);
#pragma unroll
        for (int j = 0; j < 4; j++) {
            int col = wx + j * 8 + 2 * t;
            float bc0 = bo[col], bc1 = bo[col + 1];
            float2 h0 = *(const float2*)&x[rowc * 128 + col];
            float2 h1 = *(const float2*)&x[row2c * 128 + col];
            c[i][j][0] += bc0 + h0.x;
            c[i][j][1] += bc1 + h0.y;
            c[i][j][2] += bc0 + h1.x;
            c[i][j][3] += bc1 + h1.y;
            sum[i][0] += c[i][j][0] + c[i][j][1];
            sum[i][1] += c[i][j][2] + c[i][j][3];
            sq2[i][0] = fmaf(c[i][j][0], c[i][j][0], fmaf(c[i][j][1], c[i][j][1], sq2[i][0]));
            sq2[i][1] = fmaf(c[i][j][2], c[i][j][2], fmaf(c[i][j][3], c[i][j][3], sq2[i][1]));
        }
    }
#pragma unroll
    for (int i = 0; i < 2; i++) {
#pragma unroll
        for (int hl = 0; hl < 2; hl++) {
            sum[i][hl] += __shfl_xor_sync(0xffffffffu, sum[i][hl], 1);
            sum[i][hl] += __shfl_xor_sync(0xffffffffu, sum[i][hl], 2);
            sq2[i][hl] += __shfl_xor_sync(0xffffffffu, sq2[i][hl], 1);
            sq2[i][hl] += __shfl_xor_sync(0xffffffffu, sq2[i][hl], 2);
        }
    }
    if (t == 0) {
#pragma unroll
        for (int i = 0; i < 2; i++) {
            rs[wxg][wy + i * 16 + r]     = sum[i][0];
            rs[wxg][wy + i * 16 + r + 8] = sum[i][1];
            rq[wxg][wy + i * 16 + r]     = sq2[i][0];
            rq[wxg][wy + i * 16 + r + 8] = sq2[i][1];
        }
    }
    __syncthreads();
#pragma unroll
    for (int i = 0; i < 2; i++) {
#pragma unroll
        for (int hl = 0; hl < 2; hl++) {
            int rl = wy + i * 16 + r + hl * 8;
            int row = m0 + rl;
            float s  = rs[0][rl] + rs[1][rl] + rs[2][rl] + rs[3][rl];
            float s2 = rq[0][rl] + rq[1][rl] + rq[2][rl] + rq[3][rl];
            float mean = s * (1.f / DIM);
            float var = s2 * (1.f / DIM) - mean * mean;
            float rstd = rsqrtf(var + 1e-5f);
            if (row < M) {
#pragma unroll
                for (int j = 0; j < 4; j++) {
                    int col = wx + j * 8 + 2 * t;
                    float y0 = c[i][j][hl * 2 + 0];
                    float y1 = c[i][j][hl * 2 + 1];
                    float o0 = (y0 - mean) * rstd * g1[col] + bb1[col];
                    float o1 = (y1 - mean) * rstd * g1[col + 1] + bb1[col + 1];
                    *(float2*)&gHid[row * 128 + col] = make_float2(o0, o1);
                }
            }
        }
    }
}

// ---------------------------------------------------------------------------
// fused FFN: out = LN2(gHid + gelu(gHid@W1+b1)@W2 + b2); no gF1 intermediate.
// 256 thr, 64-row tiles. For each 128-wide n-chunk: P=gelu(H@W1chunk) -> smem
// (tf32), then oacc += P @ W2chunk. Dynamic smem ~88KB.
// ---------------------------------------------------------------------------
__global__ void ffn_fused(const float* __restrict__ W1,
                          const float* __restrict__ b1v,
                          const float* __restrict__ W2,
                          const float* __restrict__ b2v,
                          const float* __restrict__ g2,
                          const float* __restrict__ bb2,
                          float* __restrict__ out, int M) {
    extern __shared__ char smem[];
    unsigned* sH = (unsigned*)smem;            // [64][132]
    unsigned* sP = sH + 64 * 132;              // [64][132]
    unsigned* sB = sP + 64 * 132;              // [32][132]
    float* rs = (float*)(sB + 32 * 132);       // [4][64]
    float* rq = rs + 4 * 64;                   // [4][64]

    int tid = threadIdx.x, lane = tid & 31, wid = tid >> 5;
    int wy = (wid & 1) * 32;                   // m-offset (2 groups)
    int wxg = wid >> 1;                        // 0..3 n-groups
    int wx = wxg * 32;
    int m0 = blockIdx.y * 64;
    int r = lane >> 2, t = lane & 3;

    // stage H tile (64 x 128) as tf32, once
#pragma unroll
    for (int l = tid; l < 2048; l += 256) {
        int m = l >> 5, kq = (l & 31) << 2;
        int gm = m0 + m; if (gm >= M) gm = M - 1;
        float4 a = *(const float4*)(&gHid[gm * 128 + kq]);
        sH[m * 132 + kq] = f2tf(a.x); sH[m * 132 + kq + 1] = f2tf(a.y);
        sH[m * 132 + kq + 2] = f2tf(a.z); sH[m * 132 + kq + 3] = f2tf(a.w);
    }
    __syncthreads();

    float oacc[2][4][4];
#pragma unroll
    for (int i = 0; i < 2; i++)
#pragma unroll
        for (int j = 0; j < 4; j++)
#pragma unroll
            for (int q = 0; q < 4; q++) oacc[i][j][q] = 0.f;

    for (int n0 = 0; n0 < 512; n0 += 128) {
        float pacc[2][4][4];
#pragma unroll
        for (int i = 0; i < 2; i++)
#pragma unroll
            for (int j = 0; j < 4; j++)
#pragma unroll
                for (int q = 0; q < 4; q++) pacc[i][j][q] = 0.f;

        // ---- ffn1: P = H @ W1[:, n0:n0+128] ----
        for (int k0 = 0; k0 < 128; k0 += 32) {
#pragma unroll
            for (int l = tid; l < 1024; l += 256) {
                int k = l >> 5, nq = (l & 31) << 2;
                float4 b = *(const float4*)(&W1[(k0 + k) * 512 + n0 + nq]);
                sB[k * 132 + nq] = f2tf(b.x); sB[k * 132 + nq + 1] = f2tf(b.y);
                sB[k * 132 + nq + 2] = f2tf(b.z); sB[k * 132 + nq + 3] = f2tf(b.w);
            }
            __syncthreads();
#pragma unroll
            for (int kk = 0; kk < 32; kk += 8) {
                unsigned af[2][4], bf[4][2];
#pragma unroll
                for (int i = 0; i < 2; i++) {
                    af[i][0] = sH[(wy + i * 16 + r) * 132 + k0 + kk + t];
                    af[i][1] = sH[(wy + i * 16 + r + 8) * 132 + k0 + kk + t];
                    af[i][2] = sH[(wy + i * 16 + r) * 132 + k0 + kk + t + 4];
                    af[i][3] = sH[(wy + i * 16 + r + 8) * 132 + k0 + kk + t + 4];
                }
#pragma unroll
                for (int j = 0; j < 4; j++) {
                    bf[j][0] = sB[(kk + t) * 132 + wx + j * 8 + r];
                    bf[j][1] = sB[(kk + t + 4) * 132 + wx + j * 8 + r];
                }
#pragma unroll
                for (int i = 0; i < 2; i++)
#pragma unroll
                    for (int j = 0; j < 4; j++) mma_tf32(pacc[i][j], af[i], bf[j]);
            }
            __syncthreads();
        }

        // ---- gelu + bias -> sP (tf32) ----
#pragma unroll
        for (int i = 0; i < 2; i++) {
#pragma unroll
            for (int j = 0; j < 4; j++) {
                int col = wx + j * 8 + 2 * t;
                float bc0 = b1v[n0 + col], bc1 = b1v[n0 + col + 1];
                float v0 = pacc[i][j][0] + bc0;
                float v1 = pacc[i][j][1] + bc1;
                float v2 = pacc[i][j][2] + bc0;
                float v3 = pacc[i][j][3] + bc1;
                v0 = 0.5f * v0 * (1.f + erff(v0 * 0.7071067811865476f));
                v1 = 0.5f * v1 * (1.f + erff(v1 * 0.7071067811865476f));
                v2 = 0.5f * v2 * (1.f + erff(v2 * 0.7071067811865476f));
                v3 = 0.5f * v3 * (1.f + erff(v3 * 0.7071067811865476f));
                int rl = wy + i * 16 + r;
                sP[rl * 132 + col]       = f2tf(v0);
                sP[rl * 132 + col + 1]   = f2tf(v1);
                sP[(rl + 8) * 132 + col]     = f2tf(v2);
                sP[(rl + 8) * 132 + col + 1] = f2tf(v3);
            }
        }
        __syncthreads();

        // ---- ffn2 partial: oacc += P @ W2[n0:n0+128, :] ----
        for (int k20 = 0; k20 < 128; k20 += 32) {
#pragma unroll
            for (int l = tid; l < 1024; l += 256) {
                int k = l >> 5, nq = (l & 31) << 2;
                float4 b = *(const float4*)(&W2[(n0 + k20 + k) * 128 + nq]);
                sB[k * 132 + nq] = f2tf(b.x); sB[k * 132 + nq + 1] = f2tf(b.y);
                sB[k * 132 + nq + 2] = f2tf(b.z); sB[k * 132 + nq + 3] = f2tf(b.w);
            }
            __syncthreads();
#pragma unroll
            for (int kk = 0; kk < 32; kk += 8) {
                unsigned af[2][4], bf[4][2];
#pragma unroll
                for (int i = 0; i < 2; i++) {
                    af[i][0] = sP[(wy + i * 16 + r) * 132 + k20 + kk + t];
                    af[i][1] = sP[(wy + i * 16 + r + 8) * 132 + k20 + kk + t];
                    af[i][2] = sP[(wy + i * 16 + r) * 132 + k20 + kk + t + 4];
                    af[i][3] = sP[(wy + i * 16 + r + 8) * 132 + k20 + kk + t + 4];
                }
#pragma unroll
                for (int j = 0; j < 4; j++) {
                    bf[j][0] = sB[(kk + t) * 132 + wx + j * 8 + r];
                    bf[j][1] = sB[(kk + t + 4) * 132 + wx + j * 8 + r];
                }
#pragma unroll
                for (int i = 0; i < 2; i++)
#pragma unroll
                    for (int j = 0; j < 4; j++) mma_tf32(oacc[i][j], af[i], bf[j]);
            }
            __syncthreads();
        }
    }

    // ---- epilogue: residual + LN2 -> out ----
    float sum[2][2] = {{0.f, 0.f}, {0.f, 0.f}};
    float sq2[2][2] = {{0.f, 0.f}, {0.f, 0.f}};
#pragma unroll
    for (int i = 0; i < 2; i++) {
        int row = m0 + wy + i * 16 + r;
        int rowc  = (row < M) ? row : (M - 1);
        int row2c = (row + 8 < M) ? (row + 8) : (M - 1);
#pragma unroll
        for (int j = 0; j < 4; j++) {
            int col = wx + j * 8 + 2 * t;
            float bc0 = b2v[col], bc1 = b2v[col + 1];
            float2 h0 = *(const float2*)&gHid[rowc * 128 + col];
            float2 h1 = *(const float2*)&gHid[row2c * 128 + col];
            oacc[i][j][0] += bc0 + h0.x;
            oacc[i][j][1] += bc1 + h0.y;
            oacc[i][j][2] += bc0 + h1.x;
            oacc[i][j][3] += bc1 + h1.y;
            sum[i][0] += oacc[i][j][0] + oacc[i][j][1];
            sum[i][1] += oacc[i][j][2] + oacc[i][j][3];
            sq2[i][0] = fmaf(oacc[i][j][0], oacc[i][j][0], fmaf(oacc[i][j][1], oacc[i][j][1], sq2[i][0]));
            sq2[i][1] = fmaf(oacc[i][j][2], oacc[i][j][2], fmaf(oacc[i][j][3], oacc[i][j][3], sq2[i][1]));
        }
    }
#pragma unroll
    for (int i = 0; i < 2; i++) {
#pragma unroll
        for (int hl = 0; hl < 2; hl++) {
            sum[i][hl] += __shfl_xor_sync(0xffffffffu, sum[i][hl], 1);
            sum[i][hl] += __shfl_xor_sync(0xffffffffu, sum[i][hl], 2);
            sq2[i][hl] += __shfl_xor_sync(0xffffffffu, sq2[i][hl], 1);
            sq2[i][hl] += __shfl_xor_sync(0xffffffffu, sq2[i][hl], 2);
        }
    }
    if (t == 0) {
#pragma unroll
        for (int i = 0; i < 2; i++) {
            rs[wxg * 64 + wy + i * 16 + r]     = sum[i][0];
            rs[wxg * 64 + wy + i * 16 + r + 8] = sum[i][1];
            rq[wxg * 64 + wy + i * 16 + r]     = sq2[i][0];
            rq[wxg * 64 + wy + i * 16 + r + 8] = sq2[i][1];
        }
    }
    __syncthreads();
#pragma unroll
    for (int i = 0; i < 2; i++) {
#pragma unroll
        for (int hl = 0; hl < 2; hl++) {
            int rl = wy + i * 16 + r + hl * 8;
            int row = m0 + rl;
            float s  = rs[rl] + rs[64 + rl] + rs[128 + rl] + rs[192 + rl];
            float s2 = rq[rl] + rq[64 + rl] + rq[128 + rl] + rq[192 + rl];
            float mean = s * (1.f / DIM);
            float var = s2 * (1.f / DIM) - mean * mean;
            float rstd = rsqrtf(var + 1e-5f);
            if (row < M) {
#pragma unroll
                for (int j = 0; j < 4; j++) {
                    int col = wx + j * 8 + 2 * t;
                    float y0 = oacc[i][j][hl * 2 + 0];
                    float y1 = oacc[i][j][hl * 2 + 1];
                    float o0 = (y0 - mean) * rstd * g2[col] + bb2[col];
                    float o1 = (y1 - mean) * rstd * g2[col + 1] + bb2[col + 1];
                    *(float2*)&out[row * 128 + col] = make_float2(o0, o1);
                }
            }
        }
    }
}

// ---------------------------------------------------------------------------
extern "C" void kernel_launch(void* const* d_in, const int* in_sizes, int n_in,
                              void* d_out, int out_size) {
    const float* x     = (const float*)d_in[0];
    const int*   ei    = (const int*)d_in[1];
    const int*   etype = (const int*)d_in[2];
    const int*   ntype = (const int*)d_in[3];
    const float* WQ    = (const float*)d_in[4];
    const float* WK    = (const float*)d_in[5];
    const float* WV    = (const float*)d_in[6];
    const float* We    = (const float*)d_in[7];
    const float* mu    = (const float*)d_in[8];
    const float* Wo    = (const float*)d_in[9];
    const float* bo    = (const float*)d_in[10];
    const float* ln1g  = (const float*)d_in[11];
    const float* ln1b  = (const float*)d_in[12];
    const float* W1    = (const float*)d_in[13];
    const float* b1    = (const float*)d_in[14];
    const float* W2    = (const float*)d_in[15];
    const float* b2    = (const float*)d_in[16];
    const float* ln2g  = (const float*)d_in[17];
    const float* ln2b  = (const float*)d_in[18];

    int N = in_sizes[0] / DIM;   // 50000
    int E = in_sizes[1] / 2;     // 800000
    int nblk = (N + 1023) / 1024;
    int mtiles128 = (N + 127) / 128;
    int mtiles64  = (N + 63) / 64;

    // dynamic smem for fused FFN: (64+64)*132 u32 + 32*132 u32 + 2*256 floats
    int fsmem = (64 * 132 + 64 * 132 + 32 * 132) * 4 + 2 * 256 * 4;
    cudaFuncSetAttribute(ffn_fused, cudaFuncAttributeMaxDynamicSharedMemorySize, fsmem);

    init_kernel<<<(N + 255) / 256, 256>>>(N);
    qkv_kt_kernel<<<N, 128>>>(x, ntype, WQ, WK, WV, We);
    hist_kernel<<<(E + 255) / 256, 256>>>(ei, E);
    scan_local_kernel<<<nblk, 1024>>>(N);
    scan_block_kernel<<<1, 64>>>(nblk);
    scan_add_kernel<<<(N + 255) / 256, 256>>>(N, E);
    fill_kernel<<<(E + 255) / 256, 256>>>(ei, etype, E);
    attn_kernel<<<N, 128>>>(mu, E);
    oproj_tc_ln1<<<dim3(1, mtiles128), 512>>>(x, Wo, bo, ln1g, ln1b, N);
    ffn_fused<<<dim3(1, mtiles64), 256, fsmem>>>(W1, b1, W2, b2, ln2g, ln2b,
                                                 (float*)d_out, N);
}

// round 9
// speedup vs baseline: 1.1891x; 1.1652x over previous
#include <cuda_runtime.h>
#include <cuda_fp16.h>
#include <math.h>

#define NN 50000
#define NE 800000
#define DIM 128
#define NH 8
#define HD 16
#define NET 5

// ---- scratch (device globals; no allocation allowed) ----
__device__ float  gQ[NN * DIM];
__device__ __half gKtH[NET * NN * DIM];  // K transformed, fp16 (64MB)
__device__ __half gVH[NN * DIM];         // V, fp16 (12.8MB)
__device__ float  gAgg[NN * DIM];
__device__ float  gHid[NN * DIM];
__device__ float  gF1[NN * 4 * DIM];
__device__ int    gEid[NE];              // packed: (etype<<20) | src
__device__ int    gCnt[NN];
__device__ int    gCur[NN];
__device__ int    gRow[NN + 1];
__device__ int    gBlkSum[64];
__device__ int    gBlkOff[64];

// ---------------------------------------------------------------------------
__global__ void init_kernel(int N) {
    int i = blockIdx.x * blockDim.x + threadIdx.x;
    if (i < N) { gCnt[i] = 0; gCur[i] = 0; }
}

// ---------------------------------------------------------------------------
// per-node-type QKV + per-edge-type K transform (all 5 types precomputed)
// ---------------------------------------------------------------------------
__global__ void qkv_kt_kernel(const float* __restrict__ x,
                              const int* __restrict__ node_type,
                              const float* __restrict__ WQ,
                              const float* __restrict__ WK,
                              const float* __restrict__ WV,
                              const float* __restrict__ We) {
    int n = blockIdx.x;
    int tid = threadIdx.x;
    __shared__ float xs[DIM];
    __shared__ float ks[DIM];
    xs[tid] = x[n * DIM + tid];
    __syncthreads();
    int t = node_type[n];
    int h = tid >> 4, f = tid & 15;
    const float* xr = xs + h * HD;
    int base = ((t * NH + h) * HD) * HD + f;
    float q = 0.f, k = 0.f, v = 0.f;
#pragma unroll
    for (int d = 0; d < HD; d++) {
        float xv = xr[d];
        q = fmaf(xv, WQ[base + d * HD], q);
        k = fmaf(xv, WK[base + d * HD], k);
        v = fmaf(xv, WV[base + d * HD], v);
    }
    gQ[n * DIM + tid] = q;
    gVH[n * DIM + tid] = __float2half(v);
    ks[tid] = k;
    __syncthreads();
    const float* kr = ks + h * HD;
#pragma unroll
    for (int et = 0; et < NET; et++) {
        const float* w = We + ((et * NH + h) * HD) * HD + f;
        float acc = 0.f;
#pragma unroll
        for (int d = 0; d < HD; d++) acc = fmaf(kr[d], w[d * HD], acc);
        gKtH[(et * NN + n) * DIM + tid] = __float2half(acc);
    }
}

// ---------------------------------------------------------------------------
// CSR build
// ---------------------------------------------------------------------------
__global__ void hist_kernel(const int* __restrict__ ei, int E) {
    int e = blockIdx.x * blockDim.x + threadIdx.x;
    if (e < E) atomicAdd(&gCnt[ei[E + e]], 1);
}

__global__ void scan_local_kernel(int N) {
    __shared__ int sh[1024];
    int t = threadIdx.x;
    int i = blockIdx.x * 1024 + t;
    int v = (i < N) ? gCnt[i] : 0;
    sh[t] = v;
    __syncthreads();
#pragma unroll
    for (int off = 1; off < 1024; off <<= 1) {
        int add = (t >= off) ? sh[t - off] : 0;
        __syncthreads();
        sh[t] += add;
        __syncthreads();
    }
    if (i < N) gRow[i] = sh[t] - v;
    if (t == 1023) gBlkSum[blockIdx.x] = sh[1023];
}

__global__ void scan_block_kernel(int nblk) {
    __shared__ int sh[64];
    int t = threadIdx.x;
    int v = (t < nblk) ? gBlkSum[t] : 0;
    sh[t] = v;
    __syncthreads();
#pragma unroll
    for (int off = 1; off < 64; off <<= 1) {
        int add = (t >= off) ? sh[t - off] : 0;
        __syncthreads();
        sh[t] += add;
        __syncthreads();
    }
    gBlkOff[t] = sh[t] - v;
}

__global__ void scan_add_kernel(int N, int E) {
    int i = blockIdx.x * blockDim.x + threadIdx.x;
    if (i < N) gRow[i] += gBlkOff[i >> 10];
    if (i == 0) gRow[N] = E;
}

// pack (etype<<20 | src): attention does ONE indexed load per edge
__global__ void fill_kernel(const int* __restrict__ ei,
                            const int* __restrict__ etype, int E) {
    int e = blockIdx.x * blockDim.x + threadIdx.x;
    if (e < E) {
        int dst = ei[E + e];
        int p = atomicAdd(&gCur[dst], 1);
        gEid[gRow[dst] + p] = (etype[e] << 20) | ei[e];
    }
}

// ---------------------------------------------------------------------------
// fused attention v3: one WARP per edge (4 edges in flight), half4 loads.
// Lane layout per warp: h = lane>>2 (8 heads), f4 = lane&3 (4 dims each).
// Per-head softmax stats in smem (warp 0 updates per tile); per-warp partial
// V accumulators merged at the end. 4x gather MLP vs block-per-edge.
// ---------------------------------------------------------------------------
__global__ void attn_kernel(const float* __restrict__ mu, int E) {
    int n = blockIdx.x;
    int tid = threadIdx.x;
    int lane = tid & 31;
    int grp = tid >> 5;             // warp index = edge slot
    int h = lane >> 2;              // head
    int f4 = lane & 3;              // dim quad within head
    int d0 = h * HD + 4 * f4;       // first of this thread's 4 dims

    __shared__ int s_pk[128];
    __shared__ float s_sc[128][9];
    __shared__ float m_sh[8], den_sh[8], scale_sh[8];
    __shared__ float s_merge[4][DIM];

    float4 q = *(const float4*)&gQ[n * DIM + d0];
    float muh[NET];
#pragma unroll
    for (int et = 0; et < NET; et++) muh[et] = mu[h * NET + et] * 0.25f;

    if (tid < 8) { m_sh[tid] = -3.402823466e38f; den_sh[tid] = 0.f; }
    float4 acc = make_float4(0.f, 0.f, 0.f, 0.f);
    __syncthreads();

    int row0 = gRow[n], row1 = gRow[n + 1];
    for (int cs = row0; cs < row1; cs += 128) {
        int c = min(128, row1 - cs);
        if (tid < c) s_pk[tid] = gEid[cs + tid];
        __syncthreads();

        // ---- phase 1: scores; warp grp handles edges j = grp, grp+4, ... ----
        for (int j = grp; j < c; j += 4) {
            int pk = s_pk[j];
            int src = pk & 0xFFFFF, et = pk >> 20;
            uint2 kraw = *(const uint2*)&gKtH[(et * NN + src) * DIM + d0];
            float2 ka = __half22float2(*(__half2*)&kraw.x);
            float2 kb = __half22float2(*(__half2*)&kraw.y);
            float s = q.x * ka.x + q.y * ka.y + q.z * kb.x + q.w * kb.y;
            s += __shfl_xor_sync(0xffffffffu, s, 1);
            s += __shfl_xor_sync(0xffffffffu, s, 2);
            if (f4 == 0) s_sc[j][h] = s * muh[et];
        }
        __syncthreads();

        // ---- phase 2: warp 0 updates per-head stats over the tile ----
        if (grp == 0) {
            float tmax = -3.402823466e38f;
            for (int j = f4; j < c; j += 4) tmax = fmaxf(tmax, s_sc[j][h]);
            tmax = fmaxf(tmax, __shfl_xor_sync(0xffffffffu, tmax, 1));
            tmax = fmaxf(tmax, __shfl_xor_sync(0xffffffffu, tmax, 2));
            float mold = m_sh[h];
            float newm = fmaxf(mold, tmax);
            float dt = 0.f;
            for (int j = f4; j < c; j += 4) {
                float w = __expf(s_sc[j][h] - newm);
                s_sc[j][h] = w;
                dt += w;
            }
            dt += __shfl_xor_sync(0xffffffffu, dt, 1);
            dt += __shfl_xor_sync(0xffffffffu, dt, 2);
            if (f4 == 0) {
                float sc = __expf(mold - newm);
                den_sh[h] = den_sh[h] * sc + dt;
                m_sh[h] = newm;
                scale_sh[h] = sc;
            }
        }
        __syncthreads();

        // ---- phase 3: rescale + weighted V accumulation ----
        float sc = scale_sh[h];
        acc.x *= sc; acc.y *= sc; acc.z *= sc; acc.w *= sc;
        for (int j = grp; j < c; j += 4) {
            int src = s_pk[j] & 0xFFFFF;
            float w = s_sc[j][h];
            uint2 vraw = *(const uint2*)&gVH[src * DIM + d0];
            float2 va = __half22float2(*(__half2*)&vraw.x);
            float2 vb = __half22float2(*(__half2*)&vraw.y);
            acc.x = fmaf(w, va.x, acc.x);
            acc.y = fmaf(w, va.y, acc.y);
            acc.z = fmaf(w, vb.x, acc.z);
            acc.w = fmaf(w, vb.y, acc.w);
        }
        __syncthreads();
    }

    // ---- merge the 4 per-warp partials ----
    *(float4*)&s_merge[grp][d0] = acc;
    __syncthreads();
    float tot = s_merge[0][tid] + s_merge[1][tid] + s_merge[2][tid] + s_merge[3][tid];
    gAgg[n * DIM + tid] = tot / (den_sh[tid >> 4] + 1e-10f);
}

// ---------------------------------------------------------------------------
// tf32 tensor-core machinery
// ---------------------------------------------------------------------------
__device__ __forceinline__ unsigned f2tf(float f) {
    unsigned r;
    asm("cvt.rna.tf32.f32 %0, %1;" : "=r"(r) : "f"(f));
    return r;
}
__device__ __forceinline__ void mma_tf32(float* c, const unsigned* a, const unsigned* b) {
    asm volatile(
        "mma.sync.aligned.m16n8k8.row.col.f32.tf32.tf32.f32 "
        "{%0,%1,%2,%3},{%4,%5,%6,%7},{%8,%9},{%0,%1,%2,%3};"
        : "+f"(c[0]), "+f"(c[1]), "+f"(c[2]), "+f"(c[3])
        : "r"(a[0]), "r"(a[1]), "r"(a[2]), "r"(a[3]), "r"(b[0]), "r"(b[1]));
}

// ---------------------------------------------------------------------------
// oproj tf32: gHid = LN1(x + gAgg @ Wo + bo); 512 thr, 128-row tiles, K=128
// ---------------------------------------------------------------------------
__global__ void oproj_tc_ln1(const float* __restrict__ x,
                             const float* __restrict__ Wo,
                             const float* __restrict__ bo,
                             const float* __restrict__ g1,
                             const float* __restrict__ bb1, int M) {
    __shared__ unsigned As[128][36];
    __shared__ unsigned Bs[32][132];
    __shared__ float rs[4][128];
    __shared__ float rq[4][128];
    int tid = threadIdx.x, lane = tid & 31, wid = tid >> 5;
    int wy = (wid & 3) * 32, wxg = wid >> 2;
    int wx = wxg * 32;
    int m0 = blockIdx.y * 128;
    int r = lane >> 2, t = lane & 3;
    float c[2][4][4];
#pragma unroll
    for (int i = 0; i < 2; i++)
#pragma unroll
        for (int j = 0; j < 4; j++)
#pragma unroll
            for (int q = 0; q < 4; q++) c[i][j][q] = 0.f;

    for (int k0 = 0; k0 < 128; k0 += 32) {
#pragma unroll
        for (int l = tid; l < 1024; l += 512) {
            int m = l >> 3, kq = (l & 7) << 2;
            int gm = m0 + m; if (gm >= M) gm = M - 1;
            float4 a = *(const float4*)(&gAgg[gm * 128 + k0 + kq]);
            As[m][kq] = f2tf(a.x); As[m][kq + 1] = f2tf(a.y);
            As[m][kq + 2] = f2tf(a.z); As[m][kq + 3] = f2tf(a.w);
        }
#pragma unroll
        for (int l = tid; l < 1024; l += 512) {
            int k = l >> 5, nq = (l & 31) << 2;
            float4 b = *(const float4*)(&Wo[(k0 + k) * 128 + nq]);
            Bs[k][nq] = f2tf(b.x); Bs[k][nq + 1] = f2tf(b.y);
            Bs[k][nq + 2] = f2tf(b.z); Bs[k][nq + 3] = f2tf(b.w);
        }
        __syncthreads();
#pragma unroll
        for (int kk = 0; kk < 32; kk += 8) {
            unsigned af[2][4], bf[4][2];
#pragma unroll
            for (int i = 0; i < 2; i++) {
                af[i][0] = As[wy + i * 16 + r][kk + t];
                af[i][1] = As[wy + i * 16 + r + 8][kk + t];
                af[i][2] = As[wy + i * 16 + r][kk + t + 4];
                af[i][3] = As[wy + i * 16 + r + 8][kk + t + 4];
            }
#pragma unroll
            for (int j = 0; j < 4; j++) {
                bf[j][0] = Bs[kk + t][wx + j * 8 + r];
                bf[j][1] = Bs[kk + t + 4][wx + j * 8 + r];
            }
#pragma unroll
            for (int i = 0; i < 2; i++)
#pragma unroll
                for (int j = 0; j < 4; j++) mma_tf32(c[i][j], af[i], bf[j]);
        }
        __syncthreads();
    }

    float sum[2][2] = {{0.f, 0.f}, {0.f, 0.f}};
    float sq2[2][2] = {{0.f, 0.f}, {0.f, 0.f}};
#pragma unroll
    for (int i = 0; i < 2; i++) {
        int row = m0 + wy + i * 16 + r;
        int rowc  = (row < M) ? row : (M - 1);
        int row2c = (row + 8 < M) ? (row + 8) : (M - 1);
#pragma unroll
        for (int j = 0; j < 4; j++) {
            int col = wx + j * 8 + 2 * t;
            float bc0 = bo[col], bc1 = bo[col + 1];
            float2 h0 = *(const float2*)&x[rowc * 128 + col];
            float2 h1 = *(const float2*)&x[row2c * 128 + col];
            c[i][j][0] += bc0 + h0.x;
            c[i][j][1] += bc1 + h0.y;
            c[i][j][2] += bc0 + h1.x;
            c[i][j][3] += bc1 + h1.y;
            sum[i][0] += c[i][j][0] + c[i][j][1];
            sum[i][1] += c[i][j][2] + c[i][j][3];
            sq2[i][0] = fmaf(c[i][j][0], c[i][j][0], fmaf(c[i][j][1], c[i][j][1], sq2[i][0]));
            sq2[i][1] = fmaf(c[i][j][2], c[i][j][2], fmaf(c[i][j][3], c[i][j][3], sq2[i][1]));
        }
    }
#pragma unroll
    for (int i = 0; i < 2; i++) {
#pragma unroll
        for (int hl = 0; hl < 2; hl++) {
            sum[i][hl] += __shfl_xor_sync(0xffffffffu, sum[i][hl], 1);
            sum[i][hl] += __shfl_xor_sync(0xffffffffu, sum[i][hl], 2);
            sq2[i][hl] += __shfl_xor_sync(0xffffffffu, sq2[i][hl], 1);
            sq2[i][hl] += __shfl_xor_sync(0xffffffffu, sq2[i][hl], 2);
        }
    }
    if (t == 0) {
#pragma unroll
        for (int i = 0; i < 2; i++) {
            rs[wxg][wy + i * 16 + r]     = sum[i][0];
            rs[wxg][wy + i * 16 + r + 8] = sum[i][1];
            rq[wxg][wy + i * 16 + r]     = sq2[i][0];
            rq[wxg][wy + i * 16 + r + 8] = sq2[i][1];
        }
    }
    __syncthreads();
#pragma unroll
    for (int i = 0; i < 2; i++) {
#pragma unroll
        for (int hl = 0; hl < 2; hl++) {
            int rl = wy + i * 16 + r + hl * 8;
            int row = m0 + rl;
            float s  = rs[0][rl] + rs[1][rl] + rs[2][rl] + rs[3][rl];
            float s2 = rq[0][rl] + rq[1][rl] + rq[2][rl] + rq[3][rl];
            float mean = s * (1.f / DIM);
            float var = s2 * (1.f / DIM) - mean * mean;
            float rstd = rsqrtf(var + 1e-5f);
            if (row < M) {
#pragma unroll
                for (int j = 0; j < 4; j++) {
                    int col = wx + j * 8 + 2 * t;
                    float y0 = c[i][j][hl * 2 + 0];
                    float y1 = c[i][j][hl * 2 + 1];
                    float o0 = (y0 - mean) * rstd * g1[col] + bb1[col];
                    float o1 = (y1 - mean) * rstd * g1[col + 1] + bb1[col + 1];
                    *(float2*)&gHid[row * 128 + col] = make_float2(o0, o1);
                }
            }
        }
    }
}

// ---------------------------------------------------------------------------
// FFN1: gF1[M,512] = gelu(gHid[M,128] @ W1 + b1); 512 thr (R6-validated)
// ---------------------------------------------------------------------------
__global__ void ffn1_tc(const float* __restrict__ W1,
                        const float* __restrict__ b1v, int M) {
    __shared__ unsigned As[128][36];
    __shared__ unsigned Bs[32][132];
    int tid = threadIdx.x, lane = tid & 31, wid = tid >> 5;
    int wy = (wid & 3) * 32, wx = (wid >> 2) * 32;
    int m0 = blockIdx.y * 128, n0 = blockIdx.x * 128;
    int r = lane >> 2, t = lane & 3;
    float c[2][4][4];
#pragma unroll
    for (int i = 0; i < 2; i++)
#pragma unroll
        for (int j = 0; j < 4; j++)
#pragma unroll
            for (int q = 0; q < 4; q++) c[i][j][q] = 0.f;

    for (int k0 = 0; k0 < 128; k0 += 32) {
#pragma unroll
        for (int l = tid; l < 1024; l += 512) {
            int m = l >> 3, kq = (l & 7) << 2;
            int gm = m0 + m; if (gm >= M) gm = M - 1;
            float4 a = *(const float4*)(&gHid[gm * 128 + k0 + kq]);
            As[m][kq] = f2tf(a.x); As[m][kq + 1] = f2tf(a.y);
            As[m][kq + 2] = f2tf(a.z); As[m][kq + 3] = f2tf(a.w);
        }
#pragma unroll
        for (int l = tid; l < 1024; l += 512) {
            int k = l >> 5, nq = (l & 31) << 2;
            float4 b = *(const float4*)(&W1[(k0 + k) * 512 + n0 + nq]);
            Bs[k][nq] = f2tf(b.x); Bs[k][nq + 1] = f2tf(b.y);
            Bs[k][nq + 2] = f2tf(b.z); Bs[k][nq + 3] = f2tf(b.w);
        }
        __syncthreads();
#pragma unroll
        for (int kk = 0; kk < 32; kk += 8) {
            unsigned af[2][4], bf[4][2];
#pragma unroll
            for (int i = 0; i < 2; i++) {
                af[i][0] = As[wy + i * 16 + r][kk + t];
                af[i][1] = As[wy + i * 16 + r + 8][kk + t];
                af[i][2] = As[wy + i * 16 + r][kk + t + 4];
                af[i][3] = As[wy + i * 16 + r + 8][kk + t + 4];
            }
#pragma unroll
            for (int j = 0; j < 4; j++) {
                bf[j][0] = Bs[kk + t][wx + j * 8 + r];
                bf[j][1] = Bs[kk + t + 4][wx + j * 8 + r];
            }
#pragma unroll
            for (int i = 0; i < 2; i++)
#pragma unroll
                for (int j = 0; j < 4; j++) mma_tf32(c[i][j], af[i], bf[j]);
        }
        __syncthreads();
    }
#pragma unroll
    for (int i = 0; i < 2; i++) {
        int row = m0 + wy + i * 16 + r;
        int row2 = row + 8;
#pragma unroll
        for (int j = 0; j < 4; j++) {
            int col = n0 + wx + j * 8 + 2 * t;
            float bc0 = b1v[col], bc1 = b1v[col + 1];
            if (row < M) {
                float v0 = c[i][j][0] + bc0;
                float v1 = c[i][j][1] + bc1;
                v0 = 0.5f * v0 * (1.f + erff(v0 * 0.7071067811865476f));
                v1 = 0.5f * v1 * (1.f + erff(v1 * 0.7071067811865476f));
                *(float2*)&gF1[row * 512 + col] = make_float2(v0, v1);
            }
            if (row2 < M) {
                float v0 = c[i][j][2] + bc0;
                float v1 = c[i][j][3] + bc1;
                v0 = 0.5f * v0 * (1.f + erff(v0 * 0.7071067811865476f));
                v1 = 0.5f * v1 * (1.f + erff(v1 * 0.7071067811865476f));
                *(float2*)&gF1[row2 * 512 + col] = make_float2(v0, v1);
            }
        }
    }
}

// ---------------------------------------------------------------------------
// FFN2: out = LN2(gHid + gF1[M,512] @ W2 + b2); 512 thr (R6-validated)
// ---------------------------------------------------------------------------
__global__ void ffn2_tc_ln2(const float* __restrict__ W2,
                            const float* __restrict__ b2v,
                            const float* __restrict__ g2,
                            const float* __restrict__ bb2,
                            float* __restrict__ out, int M) {
    __shared__ unsigned As[128][36];
    __shared__ unsigned Bs[32][132];
    __shared__ float rs[4][128];
    __shared__ float rq[4][128];
    int tid = threadIdx.x, lane = tid & 31, wid = tid >> 5;
    int wy = (wid & 3) * 32, wxg = wid >> 2;
    int wx = wxg * 32;
    int m0 = blockIdx.y * 128;
    int r = lane >> 2, t = lane & 3;
    float c[2][4][4];
#pragma unroll
    for (int i = 0; i < 2; i++)
#pragma unroll
        for (int j = 0; j < 4; j++)
#pragma unroll
            for (int q = 0; q < 4; q++) c[i][j][q] = 0.f;

    for (int k0 = 0; k0 < 512; k0 += 32) {
#pragma unroll
        for (int l = tid; l < 1024; l += 512) {
            int m = l >> 3, kq = (l & 7) << 2;
            int gm = m0 + m; if (gm >= M) gm = M - 1;
            float4 a = *(const float4*)(&gF1[gm * 512 + k0 + kq]);
            As[m][kq] = f2tf(a.x); As[m][kq + 1] = f2tf(a.y);
            As[m][kq + 2] = f2tf(a.z); As[m][kq + 3] = f2tf(a.w);
        }
#pragma unroll
        for (int l = tid; l < 1024; l += 512) {
            int k = l >> 5, nq = (l & 31) << 2;
            float4 b = *(const float4*)(&W2[(k0 + k) * 128 + nq]);
            Bs[k][nq] = f2tf(b.x); Bs[k][nq + 1] = f2tf(b.y);
            Bs[k][nq + 2] = f2tf(b.z); Bs[k][nq + 3] = f2tf(b.w);
        }
        __syncthreads();
#pragma unroll
        for (int kk = 0; kk < 32; kk += 8) {
            unsigned af[2][4], bf[4][2];
#pragma unroll
            for (int i = 0; i < 2; i++) {
                af[i][0] = As[wy + i * 16 + r][kk + t];
                af[i][1] = As[wy + i * 16 + r + 8][kk + t];
                af[i][2] = As[wy + i * 16 + r][kk + t + 4];
                af[i][3] = As[wy + i * 16 + r + 8][kk + t + 4];
            }
#pragma unroll
            for (int j = 0; j < 4; j++) {
                bf[j][0] = Bs[kk + t][wx + j * 8 + r];
                bf[j][1] = Bs[kk + t + 4][wx + j * 8 + r];
            }
#pragma unroll
            for (int i = 0; i < 2; i++)
#pragma unroll
                for (int j = 0; j < 4; j++) mma_tf32(c[i][j], af[i], bf[j]);
        }
        __syncthreads();
    }

    float sum[2][2] = {{0.f, 0.f}, {0.f, 0.f}};
    float sq2[2][2] = {{0.f, 0.f}, {0.f, 0.f}};
#pragma unroll
    for (int i = 0; i < 2; i++) {
        int row = m0 + wy + i * 16 + r;
        int rowc  = (row < M) ? row : (M - 1);
        int row2c = (row + 8 < M) ? (row + 8) : (M - 1);
#pragma unroll
        for (int j = 0; j < 4; j++) {
            int col = wx + j * 8 + 2 * t;
            float bc0 = b2v[col], bc1 = b2v[col + 1];
            float2 h0 = *(const float2*)&gHid[rowc * 128 + col];
            float2 h1 = *(const float2*)&gHid[row2c * 128 + col];
            c[i][j][0] += bc0 + h0.x;
            c[i][j][1] += bc1 + h0.y;
            c[i][j][2] += bc0 + h1.x;
            c[i][j][3] += bc1 + h1.y;
            sum[i][0] += c[i][j][0] + c[i][j][1];
            sum[i][1] += c[i][j][2] + c[i][j][3];
            sq2[i][0] = fmaf(c[i][j][0], c[i][j][0], fmaf(c[i][j][1], c[i][j][1], sq2[i][0]));
            sq2[i][1] = fmaf(c[i][j][2], c[i][j][2], fmaf(c[i][j][3], c[i][j][3], sq2[i][1]));
        }
    }
#pragma unroll
    for (int i = 0; i < 2; i++) {
#pragma unroll
        for (int hl = 0; hl < 2; hl++) {
            sum[i][hl] += __shfl_xor_sync(0xffffffffu, sum[i][hl], 1);
            sum[i][hl] += __shfl_xor_sync(0xffffffffu, sum[i][hl], 2);
            sq2[i][hl] += __shfl_xor_sync(0xffffffffu, sq2[i][hl], 1);
            sq2[i][hl] += __shfl_xor_sync(0xffffffffu, sq2[i][hl], 2);
        }
    }
    if (t == 0) {
#pragma unroll
        for (int i = 0; i < 2; i++) {
            rs[wxg][wy + i * 16 + r]     = sum[i][0];
            rs[wxg][wy + i * 16 + r + 8] = sum[i][1];
            rq[wxg][wy + i * 16 + r]     = sq2[i][0];
            rq[wxg][wy + i * 16 + r + 8] = sq2[i][1];
        }
    }
    __syncthreads();
#pragma unroll
    for (int i = 0; i < 2; i++) {
#pragma unroll
        for (int hl = 0; hl < 2; hl++) {
            int rl = wy + i * 16 + r + hl * 8;
            int row = m0 + rl;
            float s  = rs[0][rl] + rs[1][rl] + rs[2][rl] + rs[3][rl];
            float s2 = rq[0][rl] + rq[1][rl] + rq[2][rl] + rq[3][rl];
            float mean = s * (1.f / DIM);
            float var = s2 * (1.f / DIM) - mean * mean;
            float rstd = rsqrtf(var + 1e-5f);
            if (row < M) {
#pragma unroll
                for (int j = 0; j < 4; j++) {
                    int col = wx + j * 8 + 2 * t;
                    float y0 = c[i][j][hl * 2 + 0];
                    float y1 = c[i][j][hl * 2 + 1];
                    float o0 = (y0 - mean) * rstd * g2[col] + bb2[col];
                    float o1 = (y1 - mean) * rstd * g2[col + 1] + bb2[col + 1];
                    *(float2*)&out[row * 128 + col] = make_float2(o0, o1);
                }
            }
        }
    }
}

// ---------------------------------------------------------------------------
extern "C" void kernel_launch(void* const* d_in, const int* in_sizes, int n_in,
                              void* d_out, int out_size) {
    const float* x     = (const float*)d_in[0];
    const int*   ei    = (const int*)d_in[1];
    const int*   etype = (const int*)d_in[2];
    const int*   ntype = (const int*)d_in[3];
    const float* WQ    = (const float*)d_in[4];
    const float* WK    = (const float*)d_in[5];
    const float* WV    = (const float*)d_in[6];
    const float* We    = (const float*)d_in[7];
    const float* mu    = (const float*)d_in[8];
    const float* Wo    = (const float*)d_in[9];
    const float* bo    = (const float*)d_in[10];
    const float* ln1g  = (const float*)d_in[11];
    const float* ln1b  = (const float*)d_in[12];
    const float* W1    = (const float*)d_in[13];
    const float* b1    = (const float*)d_in[14];
    const float* W2    = (const float*)d_in[15];
    const float* b2    = (const float*)d_in[16];
    const float* ln2g  = (const float*)d_in[17];
    const float* ln2b  = (const float*)d_in[18];

    int N = in_sizes[0] / DIM;   // 50000
    int E = in_sizes[1] / 2;     // 800000
    int nblk = (N + 1023) / 1024;
    int mtiles = (N + 127) / 128;

    init_kernel<<<(N + 255) / 256, 256>>>(N);
    qkv_kt_kernel<<<N, 128>>>(x, ntype, WQ, WK, WV, We);
    hist_kernel<<<(E + 255) / 256, 256>>>(ei, E);
    scan_local_kernel<<<nblk, 1024>>>(N);
    scan_block_kernel<<<1, 64>>>(nblk);
    scan_add_kernel<<<(N + 255) / 256, 256>>>(N, E);
    fill_kernel<<<(E + 255) / 256, 256>>>(ei, etype, E);
    attn_kernel<<<N, 128>>>(mu, E);
    oproj_tc_ln1<<<dim3(1, mtiles), 512>>>(x, Wo, bo, ln1g, ln1b, N);
    ffn1_tc<<<dim3(4, mtiles), 512>>>(W1, b1, N);
    ffn2_tc_ln2<<<dim3(1, mtiles), 512>>>(W2, b2, ln2g, ln2b, (float*)d_out, N);
}